// round 16
// baseline (speedup 1.0000x reference)
#include <cuda_runtime.h>
#include <cstdint>

// out[b] = ||xdot[b]||^2 + (xdot[b]^T W x[b])^2
//
// Int8 2-digit split IMMA path. Per xdot-row b: xdot ~= sa[b]*(A1 + A2/256),
// per W-column n: W[:,n] ~= sb[n]*(B1 + B2/256), int8 digits. Then
//   U[b,n] ~= sa[b]*sb[n]*( A1B1 + (A1B2 + A2B1)/256 )   (q2q2'/65536 dropped)
// computed as 3 s8 GEMM products on mma.sync.m16n8k32 (s32 accum; exact) --
// HALF the mma instruction count of the bf16 3-product path that the
// (saturated) legacy-HMMA pipe was bound on. t[b] = sum_n U[b,n] x[b,n] in
// fp32 epilogue; out via modulo-32 CTA election (graph-replay safe).
//
// R15 fix: epilogue dequant scale must be indexed by GLOBAL column
// (g_sbD + n0 + col); the local index silently mis-scaled 7/8 of the tiles.
//
//  L1 stm_prep : xdot -> (A1, A2) int8 + sa + ||xdot||^2 ; W column abs-max -> sb
//  L2 stm_prep2: W -> transposed int8 digits B1, B2 [n][j]
//  L3 stm_mma  : IMMA GEMM, CTA tile 128x64, k-split 4, cp.async double buffer,
//                fused bilinear epilogue + finalize

#define NB 1024
#define ND 512
#define BM 128
#define BN 64
#define BKC 32            // k per chunk (one k32 mma step)
#define KS 128            // k per CTA (4 chunks)
#define NCH 4
#define LDU 66            // fp32 elems per Us row

// ---------------- scratch ----------------
__device__ int8_t g_Aq1[NB * ND];
__device__ int8_t g_Aq2[NB * ND];
__device__ int8_t g_Bq1[ND * ND];     // [n][j]
__device__ int8_t g_Bq2[ND * ND];
__device__ float  g_sa[NB];           // xdot row scale (delta1)
__device__ float  g_sbD[ND];          // W column scale (delta1)
__device__ float  g_sbI[ND];          // 1/delta1
__device__ float  g_norm[NB];
__device__ float  g_partial[32 * NB];
__device__ unsigned g_ctr[8];

// smem stage layout (bytes), rows are 32B data + 16B pad = 48B stride
// (8 ldmatrix row-segments at 48B stride cover all 32 banks -> conflict-free)
#define ST_A1 0
#define ST_A2 6144
#define ST_B1 12288
#define ST_B2 15360
#define STAGE 18432
#define SMEM_MMA (2 * STAGE)   // 36864; Us (128*66*4=33792) reuses smem start

// ---------------- PTX helpers ----------------
__device__ __forceinline__ uint32_t smem_u32(const void* p) {
    uint32_t a;
    asm("{ .reg .u64 t; cvta.to.shared.u64 t, %1; cvt.u32.u64 %0, t; }"
        : "=r"(a) : "l"(p));
    return a;
}
__device__ __forceinline__ void cpa16(uint32_t dst, const void* src) {
    asm volatile("cp.async.cg.shared.global [%0], [%1], 16;\n" :: "r"(dst), "l"(src));
}
#define CP_COMMIT() asm volatile("cp.async.commit_group;\n" ::: "memory")
#define CP_WAIT(n)  asm volatile("cp.async.wait_group %0;\n" :: "n"(n) : "memory")

__device__ __forceinline__ void ldsm_x4(uint32_t& r0, uint32_t& r1,
                                        uint32_t& r2, uint32_t& r3, uint32_t addr) {
    asm volatile("ldmatrix.sync.aligned.m8n8.x4.shared.b16 {%0,%1,%2,%3}, [%4];"
                 : "=r"(r0), "=r"(r1), "=r"(r2), "=r"(r3) : "r"(addr));
}
__device__ __forceinline__ void mma_s8(int* c, const uint32_t* a, const uint32_t* b) {
    asm volatile("mma.sync.aligned.m16n8k32.row.col.s32.s8.s8.s32 "
                 "{%0,%1,%2,%3}, {%4,%5,%6,%7}, {%8,%9}, {%0,%1,%2,%3};"
                 : "+r"(c[0]), "+r"(c[1]), "+r"(c[2]), "+r"(c[3])
                 : "r"(a[0]), "r"(a[1]), "r"(a[2]), "r"(a[3]), "r"(b[0]), "r"(b[1]));
}

// quantize 4 floats to digit-1 and digit-2 packed bytes
__device__ __forceinline__ void quant4(float4 v, float inv, float del, float inv256,
                                       uint32_t& p1, uint32_t& p2) {
    float q1x = rintf(v.x * inv), q1y = rintf(v.y * inv);
    float q1z = rintf(v.z * inv), q1w = rintf(v.w * inv);
    float rx = fmaf(-q1x, del, v.x), ry = fmaf(-q1y, del, v.y);
    float rz = fmaf(-q1z, del, v.z), rw = fmaf(-q1w, del, v.w);
    float q2x = fminf(fmaxf(rintf(rx * inv256), -127.f), 127.f);
    float q2y = fminf(fmaxf(rintf(ry * inv256), -127.f), 127.f);
    float q2z = fminf(fmaxf(rintf(rz * inv256), -127.f), 127.f);
    float q2w = fminf(fmaxf(rintf(rw * inv256), -127.f), 127.f);
    int a = (int)q1x, b = (int)q1y, c = (int)q1z, d = (int)q1w;
    p1 = (a & 0xFF) | ((b & 0xFF) << 8) | ((c & 0xFF) << 16) | ((d & 0xFF) << 24);
    a = (int)q2x; b = (int)q2y; c = (int)q2z; d = (int)q2w;
    p2 = (a & 0xFF) | ((b & 0xFF) << 8) | ((c & 0xFF) << 16) | ((d & 0xFF) << 24);
}

// ---------------- L1: xdot quant + norms | W column scales ----------------
__global__ __launch_bounds__(256)
void stm_prep(const float* __restrict__ xd, const float* __restrict__ W) {
    if (blockIdx.x < 128) {
        int wid = threadIdx.x >> 5, lane = threadIdx.x & 31;
        int b = blockIdx.x * 8 + wid;
        const float4* xr = (const float4*)(xd + (size_t)b * ND);
        float4 va[4];
        float amax = 0.0f, n2 = 0.0f;
#pragma unroll
        for (int p = 0; p < 4; p++) {
            float4 v = xr[lane + 32 * p];
            va[p] = v;
            amax = fmaxf(amax, fmaxf(fmaxf(fabsf(v.x), fabsf(v.y)),
                                     fmaxf(fabsf(v.z), fabsf(v.w))));
            n2 += v.x * v.x + v.y * v.y + v.z * v.z + v.w * v.w;
        }
#pragma unroll
        for (int o = 16; o > 0; o >>= 1) {
            amax = fmaxf(amax, __shfl_xor_sync(0xffffffffu, amax, o));
            n2 += __shfl_xor_sync(0xffffffffu, n2, o);
        }
        float del = amax * (1.0f / 127.0f);
        float inv = (amax > 0.0f) ? 127.0f / amax : 0.0f;
        float inv256 = inv * 256.0f;
        uint32_t* o1 = (uint32_t*)(g_Aq1 + (size_t)b * ND);
        uint32_t* o2 = (uint32_t*)(g_Aq2 + (size_t)b * ND);
#pragma unroll
        for (int p = 0; p < 4; p++) {
            uint32_t p1, p2;
            quant4(va[p], inv, del, inv256, p1, p2);
            o1[lane + 32 * p] = p1;
            o2[lane + 32 * p] = p2;
        }
        if (lane == 0) { g_norm[b] = n2; g_sa[b] = del; }
    } else {
        // W column abs-max: 32 columns per block, 64 rows per warp
        __shared__ float sm[8][32];
        int wid = threadIdx.x >> 5, lane = threadIdx.x & 31;
        int n0 = (blockIdx.x - 128) * 32;
        float m = 0.0f;
        const float* wp = W + (size_t)(wid * 64) * ND + n0 + lane;
        for (int t = 0; t < 64; t++) m = fmaxf(m, fabsf(wp[(size_t)t * ND]));
        sm[wid][lane] = m;
        __syncthreads();
        if (wid == 0) {
#pragma unroll
            for (int i = 1; i < 8; i++) m = fmaxf(m, sm[i][lane]);
            g_sbD[n0 + lane] = m * (1.0f / 127.0f);
            g_sbI[n0 + lane] = (m > 0.0f) ? 127.0f / m : 0.0f;
        }
    }
}

// ---------------- L2: W -> transposed int8 digits ----------------
__global__ __launch_bounds__(256)
void stm_prep2(const float* __restrict__ W) {
    __shared__ float s[32][33];
    int bi = blockIdx.x;
    int n0 = (bi & 15) * 32, j0 = (bi >> 4) * 32;
    int tx = threadIdx.x & 31, ty = threadIdx.x >> 5;
#pragma unroll
    for (int i = 0; i < 4; i++) {
        int r = ty + 8 * i;
        s[r][tx] = W[(size_t)(j0 + r) * ND + n0 + tx];
    }
    __syncthreads();
#pragma unroll
    for (int i = 0; i < 4; i++) {
        int n = n0 + ty + 8 * i;
        float del = g_sbD[n], inv = g_sbI[n];
        float v = s[tx][ty + 8 * i];          // = W[j0+tx][n]
        float q1 = rintf(v * inv);
        float r  = fmaf(-q1, del, v);
        float q2 = fminf(fmaxf(rintf(r * inv * 256.0f), -127.f), 127.f);
        size_t o = (size_t)n * ND + j0 + tx;
        g_Bq1[o] = (int8_t)(int)q1;
        g_Bq2[o] = (int8_t)(int)q2;
    }
}

// ---------------- L3: IMMA GEMM + fused epilogue + finalize ----------------
__device__ __forceinline__ void load_chunk(uint32_t sb, int stage, int b0, int n0,
                                           int kc, int tid) {
    uint32_t base = sb + stage * STAGE;
    {
        int row = tid >> 1, c = tid & 1;    // A rows 0..127, 16B halves
        uint32_t d = base + row * 48 + c * 16;
        size_t off = (size_t)(b0 + row) * ND + kc + c * 16;
        cpa16(d + ST_A1, g_Aq1 + off);
        cpa16(d + ST_A2, g_Aq2 + off);
    }
    if (tid < 128) {
        int row = tid >> 1, c = tid & 1;    // B rows 0..63
        uint32_t d = base + row * 48 + c * 16;
        size_t off = (size_t)(n0 + row) * ND + kc + c * 16;
        cpa16(d + ST_B1, g_Bq1 + off);
        cpa16(d + ST_B2, g_Bq2 + off);
    }
}

__global__ __launch_bounds__(256)
void stm_mma(const float* __restrict__ x, float* __restrict__ out) {
    extern __shared__ __align__(128) char smem[];
    uint32_t sb = smem_u32(smem);
    const int tid = threadIdx.x, wid = tid >> 5, lane = tid & 31;
    const int wm = wid & 3, wn = wid >> 2;       // warp tile (32m x 32n)
    const int n0 = blockIdx.x * BN;
    const int b0 = blockIdx.y * BM;
    const int kz = blockIdx.z;
    const int kbase = kz * KS;

    int chh[2][4][4], ccr[2][4][4];
#pragma unroll
    for (int i = 0; i < 2; i++)
#pragma unroll
        for (int j = 0; j < 4; j++)
#pragma unroll
            for (int r = 0; r < 4; r++) { chh[i][j][r] = 0; ccr[i][j][r] = 0; }

    load_chunk(sb, 0, b0, n0, kbase, tid);
    CP_COMMIT();

    for (int ch = 0; ch < NCH; ch++) {
        if (ch < NCH - 1) {
            load_chunk(sb, (ch + 1) & 1, b0, n0, kbase + (ch + 1) * BKC, tid);
            CP_COMMIT();
            CP_WAIT(1);
        } else {
            CP_WAIT(0);
        }
        __syncthreads();

        uint32_t st = sb + (ch & 1) * STAGE;
        // A fragments: both digits, 2 m16 blocks
        uint32_t a1[2][4], a2[2][4];
#pragma unroll
        for (int mb = 0; mb < 2; mb++) {
            int row = wm * 32 + mb * 16 + (lane & 15);
            uint32_t off = row * 48 + (lane >> 4) * 16;
            ldsm_x4(a1[mb][0], a1[mb][1], a1[mb][2], a1[mb][3], st + ST_A1 + off);
            ldsm_x4(a2[mb][0], a2[mb][1], a2[mb][2], a2[mb][3], st + ST_A2 + off);
        }
        // B fragments: both digits, 4 n8 blocks (x4 covers 2 blocks)
        uint32_t b1[4][2], b2[4][2];
#pragma unroll
        for (int np = 0; np < 2; np++) {
            int row = wn * 32 + np * 16 + ((lane >> 4) << 3) + (lane & 7);
            uint32_t off = row * 48 + ((lane >> 3) & 1) * 16;
            ldsm_x4(b1[2 * np][0], b1[2 * np][1], b1[2 * np + 1][0], b1[2 * np + 1][1],
                    st + ST_B1 + off);
            ldsm_x4(b2[2 * np][0], b2[2 * np][1], b2[2 * np + 1][0], b2[2 * np + 1][1],
                    st + ST_B2 + off);
        }
#pragma unroll
        for (int mb = 0; mb < 2; mb++)
#pragma unroll
            for (int nb = 0; nb < 4; nb++) {
                mma_s8(chh[mb][nb], a1[mb], b1[nb]);
                mma_s8(ccr[mb][nb], a1[mb], b2[nb]);
                mma_s8(ccr[mb][nb], a2[mb], b1[nb]);
            }
        __syncthreads();
    }

    // ---- epilogue: dequant (GLOBAL column scale!), store Us, dot with x ----
    float* Us = (float*)smem;                     // 128 x LDU fp32
#pragma unroll
    for (int mb = 0; mb < 2; mb++) {
        int row = wm * 32 + mb * 16 + (lane >> 2);
#pragma unroll
        for (int nb = 0; nb < 4; nb++) {
            int col = wn * 32 + nb * 8 + (lane & 3) * 2;
            float2 sc = *(const float2*)(g_sbD + n0 + col);   // <-- R15 fix
            float u0 = ((float)chh[mb][nb][0] + (float)ccr[mb][nb][0] * 0.00390625f) * sc.x;
            float u1 = ((float)chh[mb][nb][1] + (float)ccr[mb][nb][1] * 0.00390625f) * sc.y;
            float u2 = ((float)chh[mb][nb][2] + (float)ccr[mb][nb][2] * 0.00390625f) * sc.x;
            float u3 = ((float)chh[mb][nb][3] + (float)ccr[mb][nb][3] * 0.00390625f) * sc.y;
            *(float2*)(Us + row * LDU + col)       = make_float2(u0, u1);
            *(float2*)(Us + (row + 8) * LDU + col) = make_float2(u2, u3);
        }
    }
    __syncthreads();

    {
        int row = tid >> 1, half = tid & 1;       // 2 threads per row, 32 cols each
        const float4* xr = (const float4*)(x + (size_t)(b0 + row) * ND + n0 + half * 32);
        const float* ur = Us + row * LDU + half * 32;
        float s = 0.0f;
#pragma unroll
        for (int q = 0; q < 8; q++) {
            float4 v = xr[q];
            s = fmaf(ur[4 * q + 0], v.x, s);
            s = fmaf(ur[4 * q + 1], v.y, s);
            s = fmaf(ur[4 * q + 2], v.z, s);
            s = fmaf(ur[4 * q + 3], v.w, s);
        }
        s += __shfl_xor_sync(0xffffffffu, s, 1);
        if (half == 0)
            g_partial[(blockIdx.x * NCH + kz) * NB + b0 + row] = s * g_sa[b0 + row];
    }

    // ---- fused finalize: modulo-32 election (no counter reset needed) ----
    __threadfence();
    __shared__ unsigned s_done;
    if (tid == 0) s_done = atomicAdd(&g_ctr[blockIdx.y], 1u);
    __syncthreads();
    if ((s_done & 31u) == 31u) {
        __threadfence();
        if (tid < 128) {
            int b = b0 + tid;
            float t = 0.0f;
#pragma unroll
            for (int k = 0; k < 32; k++) t += g_partial[k * NB + b];
            out[b] = g_norm[b] + t * t;
        }
    }
}

// ---------------- launch ----------------
extern "C" void kernel_launch(void* const* d_in, const int* in_sizes, int n_in,
                              void* d_out, int out_size) {
    const float* x    = (const float*)d_in[0];   // [1024, 512]
    const float* xdot = (const float*)d_in[1];   // [1024, 512]
    const float* W    = (const float*)d_in[2];   // [512, 512]
    float* out = (float*)d_out;                  // [1024]

    cudaFuncSetAttribute(stm_mma, cudaFuncAttributeMaxDynamicSharedMemorySize, SMEM_MMA);

    stm_prep<<<144, 256>>>(xdot, W);
    stm_prep2<<<256, 256>>>(W);
    stm_mma<<<dim3(8, 8, 4), 256, SMEM_MMA>>>(x, out);
}

// round 17
// speedup vs baseline: 1.0743x; 1.0743x over previous
#include <cuda_runtime.h>
#include <cstdint>

// out[b] = ||xdot[b]||^2 + (xdot[b]^T W x[b])^2
//
// Int8 2-digit split IMMA path. Per xdot-row b: xdot ~= sa[b]*(A1 + A2/256),
// per W-column n: W[:,n] ~= sb[n]*(B1 + B2/256), int8 digits. Then
//   U[b,n] ~= sa[b]*sb[n]*( A1B1 + (A1B2 + A2B1)/256 )   (q2q2'/65536 dropped)
// computed as 3 s8 GEMM products on mma.sync.m16n8k32 (s32 accum; exact) --
// HALF the mma instruction count of the bf16 3-product path that the
// (saturated) legacy-HMMA pipe was bound on. t[b] = sum_n U[b,n] x[b,n] in
// fp32 epilogue; out via modulo-32 CTA election (graph-replay safe).
//
// R15 fix: epilogue dequant scale must be indexed by GLOBAL column
// (g_sbD + n0 + col); the local index silently mis-scaled 7/8 of the tiles.
//
//  L1 stm_prep : xdot -> (A1, A2) int8 + sa + ||xdot||^2 ; W column abs-max -> sb
//  L2 stm_prep2: W -> transposed int8 digits B1, B2 [n][j]
//  L3 stm_mma  : IMMA GEMM, CTA tile 128x64, k-split 4, cp.async double buffer,
//                fused bilinear epilogue + finalize

#define NB 1024
#define ND 512
#define BM 128
#define BN 64
#define BKC 32            // k per chunk (one k32 mma step)
#define KS 128            // k per CTA (4 chunks)
#define NCH 4
#define LDU 66            // fp32 elems per Us row

// ---------------- scratch ----------------
__device__ int8_t g_Aq1[NB * ND];
__device__ int8_t g_Aq2[NB * ND];
__device__ int8_t g_Bq1[ND * ND];     // [n][j]
__device__ int8_t g_Bq2[ND * ND];
__device__ float  g_sa[NB];           // xdot row scale (delta1)
__device__ float  g_sbD[ND];          // W column scale (delta1)
__device__ float  g_sbI[ND];          // 1/delta1
__device__ float  g_norm[NB];
__device__ float  g_partial[32 * NB];
__device__ unsigned g_ctr[8];

// smem stage layout (bytes), rows are 32B data + 16B pad = 48B stride
// (8 ldmatrix row-segments at 48B stride cover all 32 banks -> conflict-free)
#define ST_A1 0
#define ST_A2 6144
#define ST_B1 12288
#define ST_B2 15360
#define STAGE 18432
#define SMEM_MMA (2 * STAGE)   // 36864; Us (128*66*4=33792) reuses smem start

// ---------------- PTX helpers ----------------
__device__ __forceinline__ uint32_t smem_u32(const void* p) {
    uint32_t a;
    asm("{ .reg .u64 t; cvta.to.shared.u64 t, %1; cvt.u32.u64 %0, t; }"
        : "=r"(a) : "l"(p));
    return a;
}
__device__ __forceinline__ void cpa16(uint32_t dst, const void* src) {
    asm volatile("cp.async.cg.shared.global [%0], [%1], 16;\n" :: "r"(dst), "l"(src));
}
#define CP_COMMIT() asm volatile("cp.async.commit_group;\n" ::: "memory")
#define CP_WAIT(n)  asm volatile("cp.async.wait_group %0;\n" :: "n"(n) : "memory")

__device__ __forceinline__ void ldsm_x4(uint32_t& r0, uint32_t& r1,
                                        uint32_t& r2, uint32_t& r3, uint32_t addr) {
    asm volatile("ldmatrix.sync.aligned.m8n8.x4.shared.b16 {%0,%1,%2,%3}, [%4];"
                 : "=r"(r0), "=r"(r1), "=r"(r2), "=r"(r3) : "r"(addr));
}
__device__ __forceinline__ void mma_s8(int* c, const uint32_t* a, const uint32_t* b) {
    asm volatile("mma.sync.aligned.m16n8k32.row.col.s32.s8.s8.s32 "
                 "{%0,%1,%2,%3}, {%4,%5,%6,%7}, {%8,%9}, {%0,%1,%2,%3};"
                 : "+r"(c[0]), "+r"(c[1]), "+r"(c[2]), "+r"(c[3])
                 : "r"(a[0]), "r"(a[1]), "r"(a[2]), "r"(a[3]), "r"(b[0]), "r"(b[1]));
}

// quantize 4 floats to digit-1 and digit-2 packed bytes
__device__ __forceinline__ void quant4(float4 v, float inv, float del, float inv256,
                                       uint32_t& p1, uint32_t& p2) {
    float q1x = rintf(v.x * inv), q1y = rintf(v.y * inv);
    float q1z = rintf(v.z * inv), q1w = rintf(v.w * inv);
    float rx = fmaf(-q1x, del, v.x), ry = fmaf(-q1y, del, v.y);
    float rz = fmaf(-q1z, del, v.z), rw = fmaf(-q1w, del, v.w);
    float q2x = fminf(fmaxf(rintf(rx * inv256), -127.f), 127.f);
    float q2y = fminf(fmaxf(rintf(ry * inv256), -127.f), 127.f);
    float q2z = fminf(fmaxf(rintf(rz * inv256), -127.f), 127.f);
    float q2w = fminf(fmaxf(rintf(rw * inv256), -127.f), 127.f);
    int a = (int)q1x, b = (int)q1y, c = (int)q1z, d = (int)q1w;
    p1 = (a & 0xFF) | ((b & 0xFF) << 8) | ((c & 0xFF) << 16) | ((d & 0xFF) << 24);
    a = (int)q2x; b = (int)q2y; c = (int)q2z; d = (int)q2w;
    p2 = (a & 0xFF) | ((b & 0xFF) << 8) | ((c & 0xFF) << 16) | ((d & 0xFF) << 24);
}

// ---------------- L1: xdot quant + norms | W column scales ----------------
__global__ __launch_bounds__(256)
void stm_prep(const float* __restrict__ xd, const float* __restrict__ W) {
    if (blockIdx.x < 128) {
        int wid = threadIdx.x >> 5, lane = threadIdx.x & 31;
        int b = blockIdx.x * 8 + wid;
        const float4* xr = (const float4*)(xd + (size_t)b * ND);
        float4 va[4];
        float amax = 0.0f, n2 = 0.0f;
#pragma unroll
        for (int p = 0; p < 4; p++) {
            float4 v = xr[lane + 32 * p];
            va[p] = v;
            amax = fmaxf(amax, fmaxf(fmaxf(fabsf(v.x), fabsf(v.y)),
                                     fmaxf(fabsf(v.z), fabsf(v.w))));
            n2 += v.x * v.x + v.y * v.y + v.z * v.z + v.w * v.w;
        }
#pragma unroll
        for (int o = 16; o > 0; o >>= 1) {
            amax = fmaxf(amax, __shfl_xor_sync(0xffffffffu, amax, o));
            n2 += __shfl_xor_sync(0xffffffffu, n2, o);
        }
        float del = amax * (1.0f / 127.0f);
        float inv = (amax > 0.0f) ? 127.0f / amax : 0.0f;
        float inv256 = inv * 256.0f;
        uint32_t* o1 = (uint32_t*)(g_Aq1 + (size_t)b * ND);
        uint32_t* o2 = (uint32_t*)(g_Aq2 + (size_t)b * ND);
#pragma unroll
        for (int p = 0; p < 4; p++) {
            uint32_t p1, p2;
            quant4(va[p], inv, del, inv256, p1, p2);
            o1[lane + 32 * p] = p1;
            o2[lane + 32 * p] = p2;
        }
        if (lane == 0) { g_norm[b] = n2; g_sa[b] = del; }
    } else {
        // W column abs-max: 32 columns per block, 64 rows per warp
        __shared__ float sm[8][32];
        int wid = threadIdx.x >> 5, lane = threadIdx.x & 31;
        int n0 = (blockIdx.x - 128) * 32;
        float m = 0.0f;
        const float* wp = W + (size_t)(wid * 64) * ND + n0 + lane;
        for (int t = 0; t < 64; t++) m = fmaxf(m, fabsf(wp[(size_t)t * ND]));
        sm[wid][lane] = m;
        __syncthreads();
        if (wid == 0) {
#pragma unroll
            for (int i = 1; i < 8; i++) m = fmaxf(m, sm[i][lane]);
            g_sbD[n0 + lane] = m * (1.0f / 127.0f);
            g_sbI[n0 + lane] = (m > 0.0f) ? 127.0f / m : 0.0f;
        }
    }
}

// ---------------- L2: W -> transposed int8 digits ----------------
__global__ __launch_bounds__(256)
void stm_prep2(const float* __restrict__ W) {
    __shared__ float s[32][33];
    int bi = blockIdx.x;
    int n0 = (bi & 15) * 32, j0 = (bi >> 4) * 32;
    int tx = threadIdx.x & 31, ty = threadIdx.x >> 5;
#pragma unroll
    for (int i = 0; i < 4; i++) {
        int r = ty + 8 * i;
        s[r][tx] = W[(size_t)(j0 + r) * ND + n0 + tx];
    }
    __syncthreads();
#pragma unroll
    for (int i = 0; i < 4; i++) {
        int n = n0 + ty + 8 * i;
        float del = g_sbD[n], inv = g_sbI[n];
        float v = s[tx][ty + 8 * i];          // = W[j0+tx][n]
        float q1 = rintf(v * inv);
        float r  = fmaf(-q1, del, v);
        float q2 = fminf(fmaxf(rintf(r * inv * 256.0f), -127.f), 127.f);
        size_t o = (size_t)n * ND + j0 + tx;
        g_Bq1[o] = (int8_t)(int)q1;
        g_Bq2[o] = (int8_t)(int)q2;
    }
}

// ---------------- L3: IMMA GEMM + fused epilogue + finalize ----------------
__device__ __forceinline__ void load_chunk(uint32_t sb, int stage, int b0, int n0,
                                           int kc, int tid) {
    uint32_t base = sb + stage * STAGE;
    {
        int row = tid >> 1, c = tid & 1;    // A rows 0..127, 16B halves
        uint32_t d = base + row * 48 + c * 16;
        size_t off = (size_t)(b0 + row) * ND + kc + c * 16;
        cpa16(d + ST_A1, g_Aq1 + off);
        cpa16(d + ST_A2, g_Aq2 + off);
    }
    if (tid < 128) {
        int row = tid >> 1, c = tid & 1;    // B rows 0..63
        uint32_t d = base + row * 48 + c * 16;
        size_t off = (size_t)(n0 + row) * ND + kc + c * 16;
        cpa16(d + ST_B1, g_Bq1 + off);
        cpa16(d + ST_B2, g_Bq2 + off);
    }
}

__global__ __launch_bounds__(256)
void stm_mma(const float* __restrict__ x, float* __restrict__ out) {
    extern __shared__ __align__(128) char smem[];
    uint32_t sb = smem_u32(smem);
    const int tid = threadIdx.x, wid = tid >> 5, lane = tid & 31;
    const int wm = wid & 3, wn = wid >> 2;       // warp tile (32m x 32n)
    const int n0 = blockIdx.x * BN;
    const int b0 = blockIdx.y * BM;
    const int kz = blockIdx.z;
    const int kbase = kz * KS;

    int chh[2][4][4], ccr[2][4][4];
#pragma unroll
    for (int i = 0; i < 2; i++)
#pragma unroll
        for (int j = 0; j < 4; j++)
#pragma unroll
            for (int r = 0; r < 4; r++) { chh[i][j][r] = 0; ccr[i][j][r] = 0; }

    load_chunk(sb, 0, b0, n0, kbase, tid);
    CP_COMMIT();

    for (int ch = 0; ch < NCH; ch++) {
        if (ch < NCH - 1) {
            load_chunk(sb, (ch + 1) & 1, b0, n0, kbase + (ch + 1) * BKC, tid);
            CP_COMMIT();
            CP_WAIT(1);
        } else {
            CP_WAIT(0);
        }
        __syncthreads();

        uint32_t st = sb + (ch & 1) * STAGE;
        // A fragments: both digits, 2 m16 blocks
        uint32_t a1[2][4], a2[2][4];
#pragma unroll
        for (int mb = 0; mb < 2; mb++) {
            int row = wm * 32 + mb * 16 + (lane & 15);
            uint32_t off = row * 48 + (lane >> 4) * 16;
            ldsm_x4(a1[mb][0], a1[mb][1], a1[mb][2], a1[mb][3], st + ST_A1 + off);
            ldsm_x4(a2[mb][0], a2[mb][1], a2[mb][2], a2[mb][3], st + ST_A2 + off);
        }
        // B fragments: both digits, 4 n8 blocks (x4 covers 2 blocks)
        uint32_t b1[4][2], b2[4][2];
#pragma unroll
        for (int np = 0; np < 2; np++) {
            int row = wn * 32 + np * 16 + ((lane >> 4) << 3) + (lane & 7);
            uint32_t off = row * 48 + ((lane >> 3) & 1) * 16;
            ldsm_x4(b1[2 * np][0], b1[2 * np][1], b1[2 * np + 1][0], b1[2 * np + 1][1],
                    st + ST_B1 + off);
            ldsm_x4(b2[2 * np][0], b2[2 * np][1], b2[2 * np + 1][0], b2[2 * np + 1][1],
                    st + ST_B2 + off);
        }
#pragma unroll
        for (int mb = 0; mb < 2; mb++)
#pragma unroll
            for (int nb = 0; nb < 4; nb++) {
                mma_s8(chh[mb][nb], a1[mb], b1[nb]);
                mma_s8(ccr[mb][nb], a1[mb], b2[nb]);
                mma_s8(ccr[mb][nb], a2[mb], b1[nb]);
            }
        __syncthreads();
    }

    // ---- epilogue: dequant (GLOBAL column scale!), store Us, dot with x ----
    float* Us = (float*)smem;                     // 128 x LDU fp32
#pragma unroll
    for (int mb = 0; mb < 2; mb++) {
        int row = wm * 32 + mb * 16 + (lane >> 2);
#pragma unroll
        for (int nb = 0; nb < 4; nb++) {
            int col = wn * 32 + nb * 8 + (lane & 3) * 2;
            float2 sc = *(const float2*)(g_sbD + n0 + col);   // <-- R15 fix
            float u0 = ((float)chh[mb][nb][0] + (float)ccr[mb][nb][0] * 0.00390625f) * sc.x;
            float u1 = ((float)chh[mb][nb][1] + (float)ccr[mb][nb][1] * 0.00390625f) * sc.y;
            float u2 = ((float)chh[mb][nb][2] + (float)ccr[mb][nb][2] * 0.00390625f) * sc.x;
            float u3 = ((float)chh[mb][nb][3] + (float)ccr[mb][nb][3] * 0.00390625f) * sc.y;
            *(float2*)(Us + row * LDU + col)       = make_float2(u0, u1);
            *(float2*)(Us + (row + 8) * LDU + col) = make_float2(u2, u3);
        }
    }
    __syncthreads();

    {
        int row = tid >> 1, half = tid & 1;       // 2 threads per row, 32 cols each
        const float4* xr = (const float4*)(x + (size_t)(b0 + row) * ND + n0 + half * 32);
        const float* ur = Us + row * LDU + half * 32;
        float s = 0.0f;
#pragma unroll
        for (int q = 0; q < 8; q++) {
            float4 v = xr[q];
            s = fmaf(ur[4 * q + 0], v.x, s);
            s = fmaf(ur[4 * q + 1], v.y, s);
            s = fmaf(ur[4 * q + 2], v.z, s);
            s = fmaf(ur[4 * q + 3], v.w, s);
        }
        s += __shfl_xor_sync(0xffffffffu, s, 1);
        if (half == 0)
            g_partial[(blockIdx.x * NCH + kz) * NB + b0 + row] = s * g_sa[b0 + row];
    }

    // ---- fused finalize: modulo-32 election (no counter reset needed) ----
    __threadfence();
    __shared__ unsigned s_done;
    if (tid == 0) s_done = atomicAdd(&g_ctr[blockIdx.y], 1u);
    __syncthreads();
    if ((s_done & 31u) == 31u) {
        __threadfence();
        if (tid < 128) {
            int b = b0 + tid;
            float t = 0.0f;
#pragma unroll
            for (int k = 0; k < 32; k++) t += g_partial[k * NB + b];
            out[b] = g_norm[b] + t * t;
        }
    }
}

// ---------------- launch ----------------
extern "C" void kernel_launch(void* const* d_in, const int* in_sizes, int n_in,
                              void* d_out, int out_size) {
    const float* x    = (const float*)d_in[0];   // [1024, 512]
    const float* xdot = (const float*)d_in[1];   // [1024, 512]
    const float* W    = (const float*)d_in[2];   // [512, 512]
    float* out = (float*)d_out;                  // [1024]

    cudaFuncSetAttribute(stm_mma, cudaFuncAttributeMaxDynamicSharedMemorySize, SMEM_MMA);

    stm_prep<<<144, 256>>>(xdot, W);
    stm_prep2<<<256, 256>>>(W);
    stm_mma<<<dim3(8, 8, 4), 256, SMEM_MMA>>>(x, out);
}